// round 17
// baseline (speedup 1.0000x reference)
#include <cuda_runtime.h>
#include <cuda_bf16.h>
#include <cstdint>

#define TT   28
#define IND  28
#define HID  64
#define OUTD 10
#define BT   128
#define NT   512
#define NB   16384
#define WSTR 272                    // weight staging row stride (bytes)
#define WS_LO (256*WSTR)
#define SMEM_BYTES 139264           // max(weights 139264, Z_L1 2*128*544)

__device__ uint32_t g_h1[(size_t)TT * HID * NB];   // h1 as packed (hi,lo) bf16

typedef unsigned short u16;
typedef uint32_t u32;

__device__ __forceinline__ float tanhfast(float v){
    float r; asm("tanh.approx.f32 %0, %1;" : "=f"(r) : "f"(v)); return r;
}
__device__ __forceinline__ float sigfast(float v){
    return fmaf(0.5f, tanhfast(0.5f*v), 0.5f);
}
__device__ __forceinline__ void splitbf(float v, u16& h, u16& l){
    __nv_bfloat16 hb = __float2bfloat16(v);
    float hf = __bfloat162float(hb);
    __nv_bfloat16 lb = __float2bfloat16(v - hf);
    h = __bfloat16_as_ushort(hb);
    l = __bfloat16_as_ushort(lb);
}
// fragment-order permutation within a 16-col k-tile:
// physical position of logical col k (k in [0,16))
__device__ __forceinline__ int kperm(int k){
    return 4 * ((k & 7) >> 1) + (k & 1) + 2 * (k >> 3);
}
__device__ __forceinline__ void mma16816(float* d, const u32* a, u32 b0, u32 b1){
    asm volatile(
        "mma.sync.aligned.m16n8k16.row.col.f32.bf16.bf16.f32 "
        "{%0,%1,%2,%3}, {%4,%5,%6,%7}, {%8,%9}, {%0,%1,%2,%3};"
        : "+f"(d[0]), "+f"(d[1]), "+f"(d[2]), "+f"(d[3])
        : "r"(a[0]), "r"(a[1]), "r"(a[2]), "r"(a[3]), "r"(b0), "r"(b1));
}

// Stage inputs of timestep t into parity block (t&1) of Z (perm columns).
template<int ZSTR, bool L0, int AIN>
__device__ __forceinline__ void stage_in(char* smp, const float* x, int e0, int t, int tid)
{
    const int ZPART = BT * ZSTR;
    const int pi = t & 1;
    if constexpr (L0) {
        for (int i = tid; i < BT * IND; i += NT) {
            int b = i / IND, k = i - b * IND;
            float v = x[(size_t)(e0 + b) * (TT * IND) + t * IND + k];
            u16 hh, ll; splitbf(v, hh, ll);
            int col = AIN * pi + 16 * (k >> 4) + kperm(k & 15);
            int off = b * ZSTR + 2 * col;
            *(u16*)(smp + off) = hh;
            *(u16*)(smp + ZPART + off) = ll;
        }
    } else {
        const int u = tid >> 3, b0 = (tid & 7) * 16;
        const int col = AIN * pi + 16 * (u >> 4) + kperm(u & 15);
        const u32* src = g_h1 + ((size_t)t * HID + u) * NB + e0 + b0;
#pragma unroll
        for (int c4 = 0; c4 < 4; c4++) {
            uint4 pk = *(const uint4*)(src + 4 * c4);
            u32 vals[4] = {pk.x, pk.y, pk.z, pk.w};
#pragma unroll
            for (int r = 0; r < 4; r++) {
                int b = b0 + 4 * c4 + r;
                int off = b * ZSTR + 2 * col;
                *(u16*)(smp + off) = (u16)(vals[r] & 0xffffu);
                *(u16*)(smp + ZPART + off) = (u16)(vals[r] >> 16);
            }
        }
    }
}

// One LSTM layer with mma.sync, 16 warps (1 m-tile each), BT=128.
// Gate-pair row permutation (see R16) + fragment-order Z columns (LDS.64).
template<int KT, int KIN, int AIN, int ZSTR, bool L0>
__device__ __forceinline__ void run_layer(
    char* __restrict__ smp,
    const float* __restrict__ Wih, const float* __restrict__ Whh,
    const float* __restrict__ bih, const float* __restrict__ bhh,
    const float* __restrict__ x, int e0)
{
    constexpr int ZPART  = BT * ZSTR;
    constexpr int HBASE  = 2 * AIN;
    constexpr int ITILES = AIN / 16;

    const int tid = threadIdx.x;
    const int w   = tid >> 5;          // warp = m-tile (16)
    const int L   = tid & 31;
    const int q   = L >> 2;            // fragment row group
    const int a   = L & 3;             // fragment col-pair
    const int half = q & 1;            // gate half: 0 -> {i,f}, 1 -> {g,o}
    const int u    = 4 * w + (q >> 1); // this lane's unit
    const int ucol = 16 * (u >> 4) + kperm(u & 15);   // permuted h column

    // ---- stage split weights (gate-pair permuted rows) ----
    for (int idx = tid; idx < 256 * 128; idx += NT) {
        int rp = idx >> 7, k = idx & 127;
        int d = rp & 15;
        int orow = (2 * (d & 1) + (d >> 3)) * 64 + (4 * (rp >> 4) + ((d & 7) >> 1));
        float v = 0.0f;
        if (k < AIN) { if (k < KIN) v = Wih[orow * KIN + k]; }
        else if (k < AIN + 64) v = Whh[orow * 64 + (k - AIN)];
        u16 hh, ll; splitbf(v, hh, ll);
        *(u16*)(smp + rp * WSTR + 2 * k) = hh;
        *(u16*)(smp + WS_LO + rp * WSTR + 2 * k) = ll;
    }
    __syncthreads();

    // ---- load A fragments (held for the whole layer) ----
    u32 Ahi[KT][4], Alo[KT][4];
    {
        const int rlo = (16 * w + q) * WSTR;
        const int rhi = rlo + 8 * WSTR;
#pragma unroll
        for (int kt = 0; kt < KT; kt++) {
            const int o0 = 32 * kt + 4 * a;
            Ahi[kt][0] = *(const u32*)(smp + rlo + o0);
            Ahi[kt][1] = *(const u32*)(smp + rhi + o0);
            Ahi[kt][2] = *(const u32*)(smp + rlo + o0 + 16);
            Ahi[kt][3] = *(const u32*)(smp + rhi + o0 + 16);
            Alo[kt][0] = *(const u32*)(smp + WS_LO + rlo + o0);
            Alo[kt][1] = *(const u32*)(smp + WS_LO + rhi + o0);
            Alo[kt][2] = *(const u32*)(smp + WS_LO + rlo + o0 + 16);
            Alo[kt][3] = *(const u32*)(smp + WS_LO + rhi + o0 + 16);
        }
    }
    const float bias0 = bih[(2 * half) * 64 + u] + bhh[(2 * half) * 64 + u];
    const float bias1 = bih[(2 * half + 1) * 64 + u] + bhh[(2 * half + 1) * 64 + u];
    __syncthreads();                 // frags loaded; smem reusable as Z

    // ---- zero Z (h(-1)=0 + pads), stage t=0 ----
    for (int idx = tid; idx < 2 * ZPART / 4; idx += NT)
        ((u32*)smp)[idx] = 0;
    __syncthreads();
    stage_in<ZSTR, L0, AIN>(smp, x, e0, 0, tid);
    __syncthreads();

    float c16[16];
#pragma unroll
    for (int i = 0; i < 16; i++) c16[i] = 0.0f;

#pragma unroll 1
    for (int t = 0; t < TT; t++) {
        const int pi    = t & 1;
        const int ph_rd = (t + 1) & 1;
        const int ph_wr = t & 1;

#pragma unroll
        for (int chunk = 0; chunk < 2; chunk++) {
            float acc[8][4];
#pragma unroll
            for (int ntl = 0; ntl < 8; ntl++) {
                acc[ntl][0] = bias0; acc[ntl][1] = bias0;
                acc[ntl][2] = bias1; acc[ntl][3] = bias1;
            }

#pragma unroll
            for (int kt = 0; kt < KT; kt++) {
                const int cb = (kt < ITILES) ? (AIN * pi + 16 * kt)
                                             : (HBASE + 64 * ph_rd + 16 * (kt - ITILES));
#pragma unroll
                for (int ntl = 0; ntl < 8; ntl++) {
                    const int nt = chunk * 8 + ntl;
                    const char* zb = smp + (8 * nt + q) * ZSTR + 2 * cb + 8 * a;
                    uint2 bh = *(const uint2*)(zb);
                    uint2 bl = *(const uint2*)(zb + ZPART);
                    mma16816(acc[ntl], Ahi[kt], bh.x, bh.y);
                    mma16816(acc[ntl], Ahi[kt], bl.x, bl.y);
                    mma16816(acc[ntl], Alo[kt], bh.x, bh.y);
                }
            }

            // ---- epilogue for this chunk ----
#pragma unroll
            for (int ntl = 0; ntl < 8; ntl++) {
                const int nt = chunk * 8 + ntl;
                float av[4];
                if (half == 0) {          // gates i (j=0,1), f (j=2,3)
                    av[0] = sigfast(acc[ntl][0]); av[1] = sigfast(acc[ntl][1]);
                    av[2] = sigfast(acc[ntl][2]); av[3] = sigfast(acc[ntl][3]);
                } else {                  // gates g (j=0,1), o (j=2,3)
                    av[0] = tanhfast(acc[ntl][0]); av[1] = tanhfast(acc[ntl][1]);
                    av[2] = sigfast(acc[ntl][2]);  av[3] = sigfast(acc[ntl][3]);
                }
                float pv[4];
#pragma unroll
                for (int j = 0; j < 4; j++)
                    pv[j] = __shfl_xor_sync(0xffffffffu, av[j], 4);

                // this lane updates column b = 8nt + 2a + half
                const int jc = half;
                float vi, vf, vg, vo;
                if (half == 0) { vi = av[jc]; vf = av[2 + jc]; vg = pv[jc]; vo = pv[2 + jc]; }
                else           { vg = av[jc]; vo = av[2 + jc]; vi = pv[jc]; vf = pv[2 + jc]; }

                float cc = fmaf(vf, c16[nt], vi * vg);
                c16[nt] = cc;
                float h = vo * tanhfast(cc);
                const int b = 8 * nt + 2 * a + half;
                u16 hh, ll; splitbf(h, hh, ll);
                const int off = b * ZSTR + 2 * (HBASE + 64 * ph_wr + ucol);
                *(u16*)(smp + off) = hh;
                *(u16*)(smp + ZPART + off) = ll;
                if constexpr (L0)
                    g_h1[((size_t)t * HID + u) * NB + e0 + b] =
                        (u32)hh | ((u32)ll << 16);
            }
        }

        if (t + 1 < TT) stage_in<ZSTR, L0, AIN>(smp, x, e0, t + 1, tid);
        __syncthreads();
    }
}

__global__ void __launch_bounds__(NT, 1)
rnn_mma_kernel(const float* __restrict__ x,
               const float* __restrict__ Wih0, const float* __restrict__ Whh0,
               const float* __restrict__ bih0, const float* __restrict__ bhh0,
               const float* __restrict__ Wih1, const float* __restrict__ Whh1,
               const float* __restrict__ bih1, const float* __restrict__ bhh1,
               const float* __restrict__ Wlin, const float* __restrict__ blin,
               float* __restrict__ out)
{
    extern __shared__ char smp[];
    const int tid = threadIdx.x;
    const int e0 = blockIdx.x * BT;

    run_layer<6, 28, 32, 416, true >(smp, Wih0, Whh0, bih0, bhh0, x, e0);
    __syncthreads();
    run_layer<8, 64, 64, 544, false>(smp, Wih1, Whh1, bih1, bhh1, nullptr, e0);
    // layer1 loop ends with __syncthreads(): h2(TT-1) visible to all

    // ---- linear head: h2(TT-1) in Z h-block parity (TT-1)&1 = 1 ----
    constexpr int ZSTR1  = 544;
    constexpr int ZPART1 = BT * ZSTR1;
    constexpr int HCOL   = 128 + 64 * ((TT - 1) & 1);
    for (int i = tid; i < BT * OUTD; i += NT) {
        int b = i / OUTD, o = i - b * OUTD;
        float s = blin[o];
#pragma unroll
        for (int u = 0; u < HID; u++) {
            int col = HCOL + 16 * (u >> 4) + kperm(u & 15);
            int off = b * ZSTR1 + 2 * col;
            float h = __bfloat162float(__ushort_as_bfloat16(*(u16*)(smp + off))) +
                      __bfloat162float(__ushort_as_bfloat16(*(u16*)(smp + ZPART1 + off)));
            s += Wlin[o * HID + u] * h;
        }
        out[(size_t)(e0 + b) * OUTD + o] = s;
    }
}

extern "C" void kernel_launch(void* const* d_in, const int* in_sizes, int n_in,
                              void* d_out, int out_size)
{
    const float* x    = (const float*)d_in[0];
    const float* Wih0 = (const float*)d_in[1];
    const float* Whh0 = (const float*)d_in[2];
    const float* bih0 = (const float*)d_in[3];
    const float* bhh0 = (const float*)d_in[4];
    const float* Wih1 = (const float*)d_in[5];
    const float* Whh1 = (const float*)d_in[6];
    const float* bih1 = (const float*)d_in[7];
    const float* bhh1 = (const float*)d_in[8];
    const float* Wlin = (const float*)d_in[9];
    const float* blin = (const float*)d_in[10];
    float* out = (float*)d_out;

    int B = in_sizes[0] / (TT * IND);   // 16384
    int grid = B / BT;                  // 128

    cudaFuncSetAttribute(rnn_mma_kernel,
                         cudaFuncAttributeMaxDynamicSharedMemorySize, SMEM_BYTES);
    rnn_mma_kernel<<<grid, NT, SMEM_BYTES>>>(
        x, Wih0, Whh0, bih0, bhh0, Wih1, Whh1, bih1, bhh1, Wlin, blin, out);
}